// round 1
// baseline (speedup 1.0000x reference)
#include <cuda_runtime.h>

#define BB 2
#define CC 8
#define HH 512
#define WW 1024
#define OC 8
#define KY 3
#define KX 3
#define KK (KY*KX)

__device__ __align__(16) float4 g_xt[(size_t)BB * HH * WW * 2]; // [b][h][w][c0..3][c4..7]

__global__ __launch_bounds__(256) void transpose_bhwc(const float* __restrict__ x) {
    int idx = blockIdx.x * 256 + threadIdx.x; // over B*H*W
    if (idx >= BB * HH * WW) return;
    int b = idx >> 19;               // /(H*W) = /524288
    int hw = idx & (HH * WW - 1);
    const float* xp = x + (size_t)b * CC * HH * WW + hw;
    float4 lo, hi;
    lo.x = xp[0 * HH * WW]; lo.y = xp[1 * HH * WW];
    lo.z = xp[2 * HH * WW]; lo.w = xp[3 * HH * WW];
    hi.x = xp[4 * HH * WW]; hi.y = xp[5 * HH * WW];
    hi.z = xp[6 * HH * WW]; hi.w = xp[7 * HH * WW];
    g_xt[(size_t)idx * 2 + 0] = lo;
    g_xt[(size_t)idx * 2 + 1] = hi;
}

__global__ __launch_bounds__(256) void sconv_kernel(const float* __restrict__ wgt,
                                                    const float* __restrict__ bias,
                                                    float* __restrict__ out) {
    constexpr float PI_F = 3.14159265358979323846f;
    __shared__ float ws[KK * CC * OC]; // [k][c][o]
    __shared__ float sb[OC];

    int tid = threadIdx.y * 32 + threadIdx.x;
    for (int i = tid; i < KK * CC * OC; i += 256) {
        int k = i >> 6;
        int c = (i >> 3) & 7;
        int o = i & 7;
        ws[i] = wgt[(o * CC + c) * KK + k];
    }
    if (tid < OC) sb[tid] = bias[tid];
    __syncthreads();

    int w = blockIdx.x * 32 + threadIdx.x;
    int h = blockIdx.y * 8 + threadIdx.y;

    // az[w] = PI*((2w+1)/W - 1), po[h] = PI*(2h+1)/(2H)
    float az = PI_F * ((float)(2 * w + 1) * (1.0f / WW) - 1.0f);
    float po = PI_F * ((float)(2 * h + 1) * (0.5f / HH));
    float sa, ca, sp, cp;
    sincosf(az, &sa, &ca);
    sincosf(po, &sp, &cp);

    // tangent-plane axes
    float zx = sp * sa, zy = -cp, zz = sp * ca;   // axis_z
    float ax = ca, azc = -sa;                     // axis_x (y comp = 0)
    float yx = cp * sa, yy = sp, yz = cp * ca;    // axis_y

    const float scale = PI_F / (float)HH;
    const float gx_scale = (float)WW / (2.0f * PI_F);
    const float gy_scale = (float)HH / PI_F;

    float acc[2][OC];
#pragma unroll
    for (int b = 0; b < 2; b++)
#pragma unroll
        for (int o = 0; o < OC; o++) acc[b][o] = 0.0f;

#pragma unroll
    for (int k = 0; k < KK; k++) {
        float dx = (float)(k % KX - 1) * scale;
        float dy = (float)(k / KX - 1) * scale;
        float px = zx + ax * dx + yx * dy;
        float py = zy + yy * dy;
        float pz = zz + azc * dx + yz * dy;
        float r = sqrtf(px * px + pz * pz);
        float pol = atan2f(r, -py);
        float azm = atan2f(px, pz);
        float gx = (azm + PI_F) * gx_scale - 0.5f;
        float gy = pol * gy_scale - 0.5f;

        float x0f = floorf(gx), y0f = floorf(gy);
        float fx = gx - x0f, fy = gy - y0f;
        int ix0 = (int)x0f, iy0 = (int)y0f;
        int ix1 = ix0 + 1;
        if (ix0 < 0) ix0 += WW;
        if (ix0 >= WW) ix0 -= WW;
        if (ix1 >= WW) ix1 -= WW;
        if (ix1 < 0) ix1 += WW;
        int iy1 = iy0 + 1;
        iy0 = max(0, min(iy0, HH - 1));
        iy1 = max(0, min(iy1, HH - 1));

        float w00 = (1.0f - fx) * (1.0f - fy);
        float w01 = fx * (1.0f - fy);
        float w10 = (1.0f - fx) * fy;
        float w11 = fx * fy;

        int i00 = iy0 * WW + ix0;
        int i01 = iy0 * WW + ix1;
        int i10 = iy1 * WW + ix0;
        int i11 = iy1 * WW + ix1;

        const float* wk = &ws[k * 64];

#pragma unroll
        for (int b = 0; b < 2; b++) {
            const float4* base = &g_xt[(size_t)b * HH * WW * 2];
            float4 a0 = base[(size_t)i00 * 2 + 0];
            float4 a1 = base[(size_t)i00 * 2 + 1];
            float4 b0 = base[(size_t)i01 * 2 + 0];
            float4 b1 = base[(size_t)i01 * 2 + 1];
            float4 c0 = base[(size_t)i10 * 2 + 0];
            float4 c1 = base[(size_t)i10 * 2 + 1];
            float4 d0 = base[(size_t)i11 * 2 + 0];
            float4 d1 = base[(size_t)i11 * 2 + 1];

            float v[8];
            v[0] = a0.x * w00 + b0.x * w01 + c0.x * w10 + d0.x * w11;
            v[1] = a0.y * w00 + b0.y * w01 + c0.y * w10 + d0.y * w11;
            v[2] = a0.z * w00 + b0.z * w01 + c0.z * w10 + d0.z * w11;
            v[3] = a0.w * w00 + b0.w * w01 + c0.w * w10 + d0.w * w11;
            v[4] = a1.x * w00 + b1.x * w01 + c1.x * w10 + d1.x * w11;
            v[5] = a1.y * w00 + b1.y * w01 + c1.y * w10 + d1.y * w11;
            v[6] = a1.z * w00 + b1.z * w01 + c1.z * w10 + d1.z * w11;
            v[7] = a1.w * w00 + b1.w * w01 + c1.w * w10 + d1.w * w11;

#pragma unroll
            for (int c = 0; c < CC; c++) {
                float vc = v[c];
#pragma unroll
                for (int o = 0; o < OC; o++)
                    acc[b][o] = fmaf(vc, wk[c * 8 + o], acc[b][o]);
            }
        }
    }

#pragma unroll
    for (int b = 0; b < 2; b++)
#pragma unroll
        for (int o = 0; o < OC; o++)
            out[(size_t)((b * OC + o) * HH + h) * WW + w] = acc[b][o] + sb[o];
}

extern "C" void kernel_launch(void* const* d_in, const int* in_sizes, int n_in,
                              void* d_out, int out_size) {
    const float* x = (const float*)d_in[0];
    const float* wgt = (const float*)d_in[1];
    const float* bias = (const float*)d_in[2];
    float* out = (float*)d_out;

    int npix = BB * HH * WW;
    transpose_bhwc<<<(npix + 255) / 256, 256>>>(x);

    dim3 block(32, 8);
    dim3 grid(WW / 32, HH / 8);
    sconv_kernel<<<grid, block>>>(wgt, bias, out);
}

// round 2
// speedup vs baseline: 1.2665x; 1.2665x over previous
#include <cuda_runtime.h>

#define BB 2
#define CC 8
#define HH 512
#define WW 1024
#define OC 8
#define KY 3
#define KX 3
#define KK (KY*KX)
#define HW (HH*WW)

// Two separate channel planes: 16B/pixel each, so warp gathers over
// consecutive pixels touch 4 cache lines instead of 8.
__device__ __align__(16) float4 g_a[(size_t)BB * HW]; // channels 0..3
__device__ __align__(16) float4 g_b[(size_t)BB * HW]; // channels 4..7

__global__ __launch_bounds__(256) void transpose_bhwc(const float* __restrict__ x) {
    int idx = blockIdx.x * 256 + threadIdx.x; // over B*H*W
    if (idx >= BB * HW) return;
    int b = idx >> 19;               // /(H*W)
    int hw = idx & (HW - 1);
    const float* xp = x + (size_t)b * CC * HW + hw;
    float4 lo, hi;
    lo.x = xp[0 * HW]; lo.y = xp[1 * HW];
    lo.z = xp[2 * HW]; lo.w = xp[3 * HW];
    hi.x = xp[4 * HW]; hi.y = xp[5 * HW];
    hi.z = xp[6 * HW]; hi.w = xp[7 * HW];
    g_a[idx] = lo;
    g_b[idx] = hi;
}

__global__ __launch_bounds__(256) void sconv_kernel(const float* __restrict__ wgt,
                                                    const float* __restrict__ bias,
                                                    float* __restrict__ out) {
    constexpr float PI_F = 3.14159265358979323846f;
    __shared__ float4 ws[KK * CC * 2]; // [k][c][o0..3 | o4..7] as float4 pairs
    __shared__ float sb[OC];

    int tid = threadIdx.y * 32 + threadIdx.x;
    // ws[k*16 + c*2 + half] = weights for (k, c, o in half)
    for (int i = tid; i < KK * CC * 2; i += 256) {
        int k = i >> 4;
        int c = (i >> 1) & 7;
        int half = i & 1;
        float4 v;
        v.x = wgt[((half * 4 + 0) * CC + c) * KK + k];
        v.y = wgt[((half * 4 + 1) * CC + c) * KK + k];
        v.z = wgt[((half * 4 + 2) * CC + c) * KK + k];
        v.w = wgt[((half * 4 + 3) * CC + c) * KK + k];
        ws[i] = v;
    }
    if (tid < OC) sb[tid] = bias[tid];
    __syncthreads();

    int w = blockIdx.x * 32 + threadIdx.x;
    int h = blockIdx.y * 8 + threadIdx.y;

    float az = PI_F * ((float)(2 * w + 1) * (1.0f / WW) - 1.0f);
    float po = PI_F * ((float)(2 * h + 1) * (0.5f / HH));
    float sa, ca, sp, cp;
    sincosf(az, &sa, &ca);
    sincosf(po, &sp, &cp);

    float zx = sp * sa, zy = -cp, zz = sp * ca;   // axis_z
    float ax = ca, azc = -sa;                     // axis_x (y comp = 0)
    float yx = cp * sa, yy = sp, yz = cp * ca;    // axis_y

    const float scale = PI_F / (float)HH;
    const float gx_scale = (float)WW / (2.0f * PI_F);
    const float gy_scale = (float)HH / PI_F;

    float acc0[OC], acc1[OC];
#pragma unroll
    for (int o = 0; o < OC; o++) { acc0[o] = 0.0f; acc1[o] = 0.0f; }

#pragma unroll
    for (int k = 0; k < KK; k++) {
        float dx = (float)(k % KX - 1) * scale;
        float dy = (float)(k / KX - 1) * scale;
        float px = zx + ax * dx + yx * dy;
        float py = zy + yy * dy;
        float pz = zz + azc * dx + yz * dy;
        float r = sqrtf(px * px + pz * pz);
        float pol = atan2f(r, -py);
        float azm = atan2f(px, pz);
        float gx = (azm + PI_F) * gx_scale - 0.5f;
        float gy = pol * gy_scale - 0.5f;

        float x0f = floorf(gx), y0f = floorf(gy);
        float fx = gx - x0f, fy = gy - y0f;
        int ix0 = (int)x0f, iy0 = (int)y0f;
        int ix1 = ix0 + 1;
        if (ix0 < 0) ix0 += WW;
        if (ix0 >= WW) ix0 -= WW;
        if (ix1 >= WW) ix1 -= WW;
        if (ix1 < 0) ix1 += WW;
        int iy1 = iy0 + 1;
        iy0 = max(0, min(iy0, HH - 1));
        iy1 = max(0, min(iy1, HH - 1));

        float w00 = (1.0f - fx) * (1.0f - fy);
        float w01 = fx * (1.0f - fy);
        float w10 = (1.0f - fx) * fy;
        float w11 = fx * fy;

        int i00 = iy0 * WW + ix0;
        int i01 = iy0 * WW + ix1;
        int i10 = iy1 * WW + ix0;
        int i11 = iy1 * WW + ix1;

        const float4* wk = &ws[k * 16];

#pragma unroll
        for (int b = 0; b < 2; b++) {
            int base = b * HW;
            float4 pa0 = g_a[base + i00];
            float4 pa1 = g_a[base + i01];
            float4 pa2 = g_a[base + i10];
            float4 pa3 = g_a[base + i11];
            float4 pb0 = g_b[base + i00];
            float4 pb1 = g_b[base + i01];
            float4 pb2 = g_b[base + i10];
            float4 pb3 = g_b[base + i11];

            float v[8];
            v[0] = pa0.x * w00 + pa1.x * w01 + pa2.x * w10 + pa3.x * w11;
            v[1] = pa0.y * w00 + pa1.y * w01 + pa2.y * w10 + pa3.y * w11;
            v[2] = pa0.z * w00 + pa1.z * w01 + pa2.z * w10 + pa3.z * w11;
            v[3] = pa0.w * w00 + pa1.w * w01 + pa2.w * w10 + pa3.w * w11;
            v[4] = pb0.x * w00 + pb1.x * w01 + pb2.x * w10 + pb3.x * w11;
            v[5] = pb0.y * w00 + pb1.y * w01 + pb2.y * w10 + pb3.y * w11;
            v[6] = pb0.z * w00 + pb1.z * w01 + pb2.z * w10 + pb3.z * w11;
            v[7] = pb0.w * w00 + pb1.w * w01 + pb2.w * w10 + pb3.w * w11;

            float* acc = b ? acc1 : acc0;
#pragma unroll
            for (int c = 0; c < CC; c++) {
                float vc = v[c];
                float4 wlo = wk[c * 2 + 0];
                float4 whi = wk[c * 2 + 1];
                acc[0] = fmaf(vc, wlo.x, acc[0]);
                acc[1] = fmaf(vc, wlo.y, acc[1]);
                acc[2] = fmaf(vc, wlo.z, acc[2]);
                acc[3] = fmaf(vc, wlo.w, acc[3]);
                acc[4] = fmaf(vc, whi.x, acc[4]);
                acc[5] = fmaf(vc, whi.y, acc[5]);
                acc[6] = fmaf(vc, whi.z, acc[6]);
                acc[7] = fmaf(vc, whi.w, acc[7]);
            }
        }
    }

#pragma unroll
    for (int o = 0; o < OC; o++) {
        out[(size_t)((0 * OC + o) * HH + h) * WW + w] = acc0[o] + sb[o];
        out[(size_t)((1 * OC + o) * HH + h) * WW + w] = acc1[o] + sb[o];
    }
}

extern "C" void kernel_launch(void* const* d_in, const int* in_sizes, int n_in,
                              void* d_out, int out_size) {
    const float* x = (const float*)d_in[0];
    const float* wgt = (const float*)d_in[1];
    const float* bias = (const float*)d_in[2];
    float* out = (float*)d_out;

    int npix = BB * HW;
    transpose_bhwc<<<(npix + 255) / 256, 256>>>(x);

    dim3 block(32, 8);
    dim3 grid(WW / 32, HH / 8);
    sconv_kernel<<<grid, block>>>(wgt, bias, out);
}

// round 3
// speedup vs baseline: 1.5834x; 1.2502x over previous
#include <cuda_runtime.h>
#include <cuda_fp16.h>

#define BB 2
#define CC 8
#define HH 512
#define WW 1024
#define OC 8
#define KY 3
#define KX 3
#define KK (KY*KX)
#define HW (HH*WW)

// fp16 transposed input: [b][pix] -> 8 channels packed in 16 bytes.
__device__ __align__(16) uint4 g_h[(size_t)BB * HW];

__global__ __launch_bounds__(256) void transpose_h(const float* __restrict__ x) {
    int idx = blockIdx.x * 256 + threadIdx.x; // over B*H*W
    if (idx >= BB * HW) return;
    int b = idx >> 19;
    int hw = idx & (HW - 1);
    const float* xp = x + (size_t)b * CC * HW + hw;
    __half2 p0 = __floats2half2_rn(xp[0 * HW], xp[1 * HW]);
    __half2 p1 = __floats2half2_rn(xp[2 * HW], xp[3 * HW]);
    __half2 p2 = __floats2half2_rn(xp[4 * HW], xp[5 * HW]);
    __half2 p3 = __floats2half2_rn(xp[6 * HW], xp[7 * HW]);
    uint4 q;
    q.x = *reinterpret_cast<unsigned*>(&p0);
    q.y = *reinterpret_cast<unsigned*>(&p1);
    q.z = *reinterpret_cast<unsigned*>(&p2);
    q.w = *reinterpret_cast<unsigned*>(&p3);
    g_h[idx] = q;
}

__device__ __forceinline__ void bilin8(uint4 a, uint4 b, uint4 c, uint4 d,
                                       __half2 w0, __half2 w1, __half2 w2, __half2 w3,
                                       float* v) {
    const __half2* A = reinterpret_cast<const __half2*>(&a);
    const __half2* B = reinterpret_cast<const __half2*>(&b);
    const __half2* C = reinterpret_cast<const __half2*>(&c);
    const __half2* D = reinterpret_cast<const __half2*>(&d);
#pragma unroll
    for (int j = 0; j < 4; j++) {
        __half2 t = __hmul2(A[j], w0);
        t = __hfma2(B[j], w1, t);
        t = __hfma2(C[j], w2, t);
        t = __hfma2(D[j], w3, t);
        float2 f = __half22float2(t);
        v[2 * j]     = f.x;
        v[2 * j + 1] = f.y;
    }
}

__global__ __launch_bounds__(256) void sconv_kernel(const float* __restrict__ wgt,
                                                    const float* __restrict__ bias,
                                                    float* __restrict__ out) {
    constexpr float PI_F = 3.14159265358979323846f;
    __shared__ float4 ws[KK * CC * 2]; // [k][c][o0..3 | o4..7]
    __shared__ float sb[OC];

    int tid = threadIdx.y * 32 + threadIdx.x;
    for (int i = tid; i < KK * CC * 2; i += 256) {
        int k = i >> 4;
        int c = (i >> 1) & 7;
        int half = i & 1;
        float4 v;
        v.x = wgt[((half * 4 + 0) * CC + c) * KK + k];
        v.y = wgt[((half * 4 + 1) * CC + c) * KK + k];
        v.z = wgt[((half * 4 + 2) * CC + c) * KK + k];
        v.w = wgt[((half * 4 + 3) * CC + c) * KK + k];
        ws[i] = v;
    }
    if (tid < OC) sb[tid] = bias[tid];
    __syncthreads();

    int w = blockIdx.x * 32 + threadIdx.x;
    int h = blockIdx.y * 8 + threadIdx.y;

    float az = PI_F * ((float)(2 * w + 1) * (1.0f / WW) - 1.0f);
    float po = PI_F * ((float)(2 * h + 1) * (0.5f / HH));
    float sa, ca, sp, cp;
    sincosf(az, &sa, &ca);
    sincosf(po, &sp, &cp);

    float zx = sp * sa, zy = -cp, zz = sp * ca;   // axis_z
    float ax = ca, azc = -sa;                     // axis_x (y comp = 0)
    float yx = cp * sa, yy = sp, yz = cp * ca;    // axis_y

    const float scale = PI_F / (float)HH;
    const float gx_scale = (float)WW / (2.0f * PI_F);
    const float gy_scale = (float)HH / PI_F;

    float acc0[OC], acc1[OC];
#pragma unroll
    for (int o = 0; o < OC; o++) { acc0[o] = 0.0f; acc1[o] = 0.0f; }

#pragma unroll
    for (int k = 0; k < KK; k++) {
        float dx = (float)(k % KX - 1) * scale;
        float dy = (float)(k / KX - 1) * scale;
        float px = zx + ax * dx + yx * dy;
        float py = zy + yy * dy;
        float pz = zz + azc * dx + yz * dy;
        float r = sqrtf(px * px + pz * pz);
        float pol = atan2f(r, -py);
        float azm = atan2f(px, pz);
        float gx = (azm + PI_F) * gx_scale - 0.5f;
        float gy = pol * gy_scale - 0.5f;

        float x0f = floorf(gx), y0f = floorf(gy);
        float fx = gx - x0f, fy = gy - y0f;
        int ix0 = (int)x0f, iy0 = (int)y0f;
        int ix1 = ix0 + 1;
        if (ix0 < 0) ix0 += WW;
        if (ix0 >= WW) ix0 -= WW;
        if (ix1 >= WW) ix1 -= WW;
        if (ix1 < 0) ix1 += WW;
        int iy1 = iy0 + 1;
        iy0 = max(0, min(iy0, HH - 1));
        iy1 = max(0, min(iy1, HH - 1));

        float w00 = (1.0f - fx) * (1.0f - fy);
        float w01 = fx * (1.0f - fy);
        float w10 = (1.0f - fx) * fy;
        float w11 = fx * fy;
        __half2 hw00 = __float2half2_rn(w00);
        __half2 hw01 = __float2half2_rn(w01);
        __half2 hw10 = __float2half2_rn(w10);
        __half2 hw11 = __float2half2_rn(w11);

        int i00 = iy0 * WW + ix0;
        int i01 = iy0 * WW + ix1;
        int i10 = iy1 * WW + ix0;
        int i11 = iy1 * WW + ix1;

        // gather taps for both batches (one LDG.128 per tap per batch)
        uint4 q00 = g_h[i00],       q01 = g_h[i01];
        uint4 q10 = g_h[i10],       q11 = g_h[i11];
        uint4 r00 = g_h[HW + i00],  r01 = g_h[HW + i01];
        uint4 r10 = g_h[HW + i10],  r11 = g_h[HW + i11];

        float v0[8], v1[8];
        bilin8(q00, q01, q10, q11, hw00, hw01, hw10, hw11, v0);
        bilin8(r00, r01, r10, r11, hw00, hw01, hw10, hw11, v1);

        const float4* wk = &ws[k * 16];
#pragma unroll
        for (int c = 0; c < CC; c++) {
            float4 wlo = wk[c * 2 + 0];
            float4 whi = wk[c * 2 + 1];
            float a = v0[c], b = v1[c];
            acc0[0] = fmaf(a, wlo.x, acc0[0]);  acc1[0] = fmaf(b, wlo.x, acc1[0]);
            acc0[1] = fmaf(a, wlo.y, acc0[1]);  acc1[1] = fmaf(b, wlo.y, acc1[1]);
            acc0[2] = fmaf(a, wlo.z, acc0[2]);  acc1[2] = fmaf(b, wlo.z, acc1[2]);
            acc0[3] = fmaf(a, wlo.w, acc0[3]);  acc1[3] = fmaf(b, wlo.w, acc1[3]);
            acc0[4] = fmaf(a, whi.x, acc0[4]);  acc1[4] = fmaf(b, whi.x, acc1[4]);
            acc0[5] = fmaf(a, whi.y, acc0[5]);  acc1[5] = fmaf(b, whi.y, acc1[5]);
            acc0[6] = fmaf(a, whi.z, acc0[6]);  acc1[6] = fmaf(b, whi.z, acc1[6]);
            acc0[7] = fmaf(a, whi.w, acc0[7]);  acc1[7] = fmaf(b, whi.w, acc1[7]);
        }
    }

#pragma unroll
    for (int o = 0; o < OC; o++) {
        out[(size_t)((0 * OC + o) * HH + h) * WW + w] = acc0[o] + sb[o];
        out[(size_t)((1 * OC + o) * HH + h) * WW + w] = acc1[o] + sb[o];
    }
}

extern "C" void kernel_launch(void* const* d_in, const int* in_sizes, int n_in,
                              void* d_out, int out_size) {
    const float* x = (const float*)d_in[0];
    const float* wgt = (const float*)d_in[1];
    const float* bias = (const float*)d_in[2];
    float* out = (float*)d_out;

    int npix = BB * HW;
    transpose_h<<<(npix + 255) / 256, 256>>>(x);

    dim3 block(32, 8);
    dim3 grid(WW / 32, HH / 8);
    sconv_kernel<<<grid, block>>>(wgt, bias, out);
}

// round 4
// speedup vs baseline: 1.9300x; 1.2189x over previous
#include <cuda_runtime.h>
#include <cuda_fp16.h>

#define BB 2
#define CC 8
#define HH 512
#define WW 1024
#define OC 8
#define KY 3
#define KX 3
#define KK (KY*KX)
#define HW (HH*WW)

// fp16 transposed input: [b][pix] -> 8 channels packed in 16 bytes.
__device__ __align__(16) uint4 g_h[(size_t)BB * HW];

__global__ __launch_bounds__(256) void transpose_h(const float* __restrict__ x) {
    int idx = blockIdx.x * 256 + threadIdx.x;
    if (idx >= BB * HW) return;
    int b = idx >> 19;
    int hw = idx & (HW - 1);
    const float* xp = x + (size_t)b * CC * HW + hw;
    __half2 p0 = __floats2half2_rn(xp[0 * HW], xp[1 * HW]);
    __half2 p1 = __floats2half2_rn(xp[2 * HW], xp[3 * HW]);
    __half2 p2 = __floats2half2_rn(xp[4 * HW], xp[5 * HW]);
    __half2 p3 = __floats2half2_rn(xp[6 * HW], xp[7 * HW]);
    uint4 q;
    q.x = *reinterpret_cast<unsigned*>(&p0);
    q.y = *reinterpret_cast<unsigned*>(&p1);
    q.z = *reinterpret_cast<unsigned*>(&p2);
    q.w = *reinterpret_cast<unsigned*>(&p3);
    g_h[idx] = q;
}

// atan2 with single fast division + Cephes poly on [0, tan(pi/8)].
// Peak error ~1e-7 rad -> ~2e-4 pixel, far below the fp16 noise floor.
__device__ __forceinline__ float fast_atan2f(float y, float x) {
    float ay = fabsf(y), ax = fabsf(x);
    float n = fminf(ay, ax), d = fmaxf(ay, ax);
    bool big = n > 0.4142135624f * d;
    float num = big ? (n - d) : n;
    float den = big ? (n + d) : d;
    float t = __fdividef(num, den);
    float z = t * t;
    float p = fmaf(fmaf(fmaf(8.05374449538e-2f, z, -1.38776856032e-1f), z,
                        1.99777106478e-1f), z, -3.33329491539e-1f);
    float r = fmaf(p * z, t, t);
    if (big) r += 0.78539816339744831f;
    if (ay > ax) r = 1.57079632679489662f - r;
    if (x < 0.0f) r = 3.14159265358979323f - r;
    return copysignf(r, y);
}

__device__ __forceinline__ void bilin8(uint4 a, uint4 b, uint4 c, uint4 d,
                                       __half2 w0, __half2 w1, __half2 w2, __half2 w3,
                                       float* v) {
    const __half2* A = reinterpret_cast<const __half2*>(&a);
    const __half2* B = reinterpret_cast<const __half2*>(&b);
    const __half2* C = reinterpret_cast<const __half2*>(&c);
    const __half2* D = reinterpret_cast<const __half2*>(&d);
#pragma unroll
    for (int j = 0; j < 4; j++) {
        __half2 t = __hmul2(A[j], w0);
        t = __hfma2(B[j], w1, t);
        t = __hfma2(C[j], w2, t);
        t = __hfma2(D[j], w3, t);
        float2 f = __half22float2(t);
        v[2 * j]     = f.x;
        v[2 * j + 1] = f.y;
    }
}

__device__ __forceinline__ unsigned long long dup_f32x2(float f) {
    unsigned long long r;
    asm("mov.b64 %0, {%1, %1};" : "=l"(r) : "f"(f));
    return r;
}

__device__ __forceinline__ void ffma2(unsigned long long& acc,
                                      unsigned long long a, unsigned long long b) {
    asm("fma.rn.f32x2 %0, %1, %2, %0;" : "+l"(acc) : "l"(a), "l"(b));
}

__global__ __launch_bounds__(256) void sconv_kernel(const float* __restrict__ wgt,
                                                    const float* __restrict__ bias,
                                                    float* __restrict__ out) {
    constexpr float PI_F = 3.14159265358979323846f;
    __shared__ __align__(16) float ws[KK * CC * OC]; // [k][c][o], o-pairs adjacent
    __shared__ float sb[OC];

    int tid = threadIdx.y * 32 + threadIdx.x;
    for (int i = tid; i < KK * CC * OC; i += 256) {
        int k = i >> 6;
        int c = (i >> 3) & 7;
        int o = i & 7;
        ws[i] = wgt[(o * CC + c) * KK + k];
    }
    if (tid < OC) sb[tid] = bias[tid];
    __syncthreads();

    int w = blockIdx.x * 32 + threadIdx.x;
    int h = blockIdx.y * 8 + threadIdx.y;

    float az = PI_F * ((float)(2 * w + 1) * (1.0f / WW) - 1.0f);
    float po = PI_F * ((float)(2 * h + 1) * (0.5f / HH));
    float sa, ca, sp, cp;
    sincosf(az, &sa, &ca);
    sincosf(po, &sp, &cp);

    float zx = sp * sa, zy = -cp, zz = sp * ca;   // axis_z
    float ax = ca, azc = -sa;                     // axis_x (y comp = 0)
    float yx = cp * sa, yy = sp, yz = cp * ca;    // axis_y

    const float scale = PI_F / (float)HH;
    const float gx_scale = (float)WW / (2.0f * PI_F);
    const float gy_scale = (float)HH / PI_F;

    // packed accumulators: a0[j] = (acc0[2j], acc0[2j+1]), same for batch 1
    unsigned long long a0[4] = {0ull, 0ull, 0ull, 0ull};
    unsigned long long a1[4] = {0ull, 0ull, 0ull, 0ull};

    const ulonglong2* wsp = reinterpret_cast<const ulonglong2*>(ws);

#pragma unroll
    for (int k = 0; k < KK; k++) {
        float dx = (float)(k % KX - 1) * scale;
        float dy = (float)(k / KX - 1) * scale;
        float px = zx + ax * dx + yx * dy;
        float py = zy + yy * dy;
        float pz = zz + azc * dx + yz * dy;
        float r = sqrtf(px * px + pz * pz);
        float pol = fast_atan2f(r, -py);
        float azm = fast_atan2f(px, pz);
        float gx = (azm + PI_F) * gx_scale - 0.5f;
        float gy = pol * gy_scale - 0.5f;

        int ix0 = __float2int_rd(gx);
        int iy0 = __float2int_rd(gy);
        float fx = gx - (float)ix0;
        float fy = gy - (float)iy0;
        int ix1 = ix0 + 1;
        if (ix0 < 0) ix0 += WW;       // gx > -0.5, so only the -1 case
        if (ix1 >= WW) ix1 -= WW;
        int iy1 = iy0 + 1;
        iy0 = max(iy0, 0);            // gy in [-0.5, 511.5]
        iy1 = min(iy1, HH - 1);

        float w00 = (1.0f - fx) * (1.0f - fy);
        float w01 = fx * (1.0f - fy);
        float w10 = (1.0f - fx) * fy;
        float w11 = fx * fy;
        __half2 hw00 = __float2half2_rn(w00);
        __half2 hw01 = __float2half2_rn(w01);
        __half2 hw10 = __float2half2_rn(w10);
        __half2 hw11 = __float2half2_rn(w11);

        int i00 = iy0 * WW + ix0;
        int i01 = iy0 * WW + ix1;
        int i10 = iy1 * WW + ix0;
        int i11 = iy1 * WW + ix1;

        uint4 q00 = g_h[i00],       q01 = g_h[i01];
        uint4 q10 = g_h[i10],       q11 = g_h[i11];
        uint4 r00 = g_h[HW + i00],  r01 = g_h[HW + i01];
        uint4 r10 = g_h[HW + i10],  r11 = g_h[HW + i11];

        float v0[8], v1[8];
        bilin8(q00, q01, q10, q11, hw00, hw01, hw10, hw11, v0);
        bilin8(r00, r01, r10, r11, hw00, hw01, hw10, hw11, v1);

        const ulonglong2* wk = wsp + k * 16; // 2 ulonglong2 per c = 4 o-pairs
#pragma unroll
        for (int c = 0; c < CC; c++) {
            ulonglong2 wa = wk[c * 2 + 0]; // (o0,o1),(o2,o3)
            ulonglong2 wb = wk[c * 2 + 1]; // (o4,o5),(o6,o7)
            unsigned long long vd0 = dup_f32x2(v0[c]);
            unsigned long long vd1 = dup_f32x2(v1[c]);
            ffma2(a0[0], vd0, wa.x);
            ffma2(a0[1], vd0, wa.y);
            ffma2(a0[2], vd0, wb.x);
            ffma2(a0[3], vd0, wb.y);
            ffma2(a1[0], vd1, wa.x);
            ffma2(a1[1], vd1, wa.y);
            ffma2(a1[2], vd1, wb.x);
            ffma2(a1[3], vd1, wb.y);
        }
    }

#pragma unroll
    for (int j = 0; j < 4; j++) {
        float l0, h0, l1, h1;
        asm("mov.b64 {%0, %1}, %2;" : "=f"(l0), "=f"(h0) : "l"(a0[j]));
        asm("mov.b64 {%0, %1}, %2;" : "=f"(l1), "=f"(h1) : "l"(a1[j]));
        int o = 2 * j;
        out[(size_t)((0 * OC + o) * HH + h) * WW + w]     = l0 + sb[o];
        out[(size_t)((0 * OC + o + 1) * HH + h) * WW + w] = h0 + sb[o + 1];
        out[(size_t)((1 * OC + o) * HH + h) * WW + w]     = l1 + sb[o];
        out[(size_t)((1 * OC + o + 1) * HH + h) * WW + w] = h1 + sb[o + 1];
    }
}

extern "C" void kernel_launch(void* const* d_in, const int* in_sizes, int n_in,
                              void* d_out, int out_size) {
    const float* x = (const float*)d_in[0];
    const float* wgt = (const float*)d_in[1];
    const float* bias = (const float*)d_in[2];
    float* out = (float*)d_out;

    int npix = BB * HW;
    transpose_h<<<(npix + 255) / 256, 256>>>(x);

    dim3 block(32, 8);
    dim3 grid(WW / 32, HH / 8);
    sconv_kernel<<<grid, block>>>(wgt, bias, out);
}

// round 5
// speedup vs baseline: 2.1379x; 1.1078x over previous
#include <cuda_runtime.h>
#include <cuda_fp16.h>

#define BB 2
#define CC 8
#define HH 512
#define WW 1024
#define OC 8
#define KY 3
#define KX 3
#define KK (KY*KX)
#define HW (HH*WW)

// fp16 transposed input: [b][pix] -> 8 channels packed in 16 bytes.
__device__ __align__(16) uint4 g_h[(size_t)BB * HW];

__global__ __launch_bounds__(256) void transpose_h(const float* __restrict__ x) {
    int idx = blockIdx.x * 256 + threadIdx.x;
    if (idx >= BB * HW) return;
    int b = idx >> 19;
    int hw = idx & (HW - 1);
    const float* xp = x + (size_t)b * CC * HW + hw;
    __half2 p0 = __floats2half2_rn(xp[0 * HW], xp[1 * HW]);
    __half2 p1 = __floats2half2_rn(xp[2 * HW], xp[3 * HW]);
    __half2 p2 = __floats2half2_rn(xp[4 * HW], xp[5 * HW]);
    __half2 p3 = __floats2half2_rn(xp[6 * HW], xp[7 * HW]);
    uint4 q;
    q.x = *reinterpret_cast<unsigned*>(&p0);
    q.y = *reinterpret_cast<unsigned*>(&p1);
    q.z = *reinterpret_cast<unsigned*>(&p2);
    q.w = *reinterpret_cast<unsigned*>(&p3);
    g_h[idx] = q;
}

// atan2 with single fast division + Cephes poly. ~1e-7 rad error.
__device__ __forceinline__ float fast_atan2f(float y, float x) {
    float ay = fabsf(y), ax = fabsf(x);
    float n = fminf(ay, ax), d = fmaxf(ay, ax);
    bool big = n > 0.4142135624f * d;
    float num = big ? (n - d) : n;
    float den = big ? (n + d) : d;
    float t = __fdividef(num, den);
    float z = t * t;
    float p = fmaf(fmaf(fmaf(8.05374449538e-2f, z, -1.38776856032e-1f), z,
                        1.99777106478e-1f), z, -3.33329491539e-1f);
    float r = fmaf(p * z, t, t);
    if (big) r += 0.78539816339744831f;
    if (ay > ax) r = 1.57079632679489662f - r;
    if (x < 0.0f) r = 3.14159265358979323f - r;
    return copysignf(r, y);
}

__device__ __forceinline__ void bilin8(uint4 a, uint4 b, uint4 c, uint4 d,
                                       __half2 w0, __half2 w1, __half2 w2, __half2 w3,
                                       float* v) {
    const __half2* A = reinterpret_cast<const __half2*>(&a);
    const __half2* B = reinterpret_cast<const __half2*>(&b);
    const __half2* C = reinterpret_cast<const __half2*>(&c);
    const __half2* D = reinterpret_cast<const __half2*>(&d);
#pragma unroll
    for (int j = 0; j < 4; j++) {
        __half2 t = __hmul2(A[j], w0);
        t = __hfma2(B[j], w1, t);
        t = __hfma2(C[j], w2, t);
        t = __hfma2(D[j], w3, t);
        float2 f = __half22float2(t);
        v[2 * j]     = f.x;
        v[2 * j + 1] = f.y;
    }
}

__device__ __forceinline__ unsigned long long dup_f32x2(float f) {
    unsigned long long r;
    asm("mov.b64 %0, {%1, %1};" : "=l"(r) : "f"(f));
    return r;
}

__device__ __forceinline__ void ffma2(unsigned long long& acc,
                                      unsigned long long a, unsigned long long b) {
    asm("fma.rn.f32x2 %0, %1, %2, %0;" : "+l"(acc) : "l"(a), "l"(b));
}

__global__ __launch_bounds__(256, 4) void sconv_kernel(const float* __restrict__ wgt,
                                                       const float* __restrict__ bias,
                                                       float* __restrict__ out) {
    constexpr float PI_F = 3.14159265358979323846f;
    __shared__ __align__(16) float ws[KK * CC * OC]; // [k][c][o]
    __shared__ __align__(16) float4 s_map[8][KK];    // {dgx, fy, iy0*W, iy1*W}
    __shared__ float sb[OC];

    int tid = threadIdx.y * 32 + threadIdx.x;
    for (int i = tid; i < KK * CC * OC; i += 256) {
        int k = i >> 6;
        int c = (i >> 3) & 7;
        int o = i & 7;
        ws[i] = wgt[(o * CC + c) * KK + k];
    }
    if (tid < OC) sb[tid] = bias[tid];

    // Per-(h,k) geometry: gx = w + dgx(h,k); gy depends on (h,k) only.
    if (tid < 8 * KK) {
        int ty = tid / KK;
        int k = tid - ty * KK;
        int h = blockIdx.y * 8 + ty;
        const float scale = PI_F / (float)HH;
        const float gx_scale = (float)WW / (2.0f * PI_F);
        const float gy_scale = (float)HH / PI_F;
        float po = PI_F * ((float)(2 * h + 1) * (0.5f / HH));
        float sp, cp;
        sincosf(po, &sp, &cp);
        float dx = (float)(k % KX - 1) * scale;
        float dy = (float)(k / KX - 1) * scale;
        float alpha = fmaf(cp, dy, sp);   // sp + cp*dy
        float gamma = fmaf(-sp, dy, cp);  // cp - sp*dy
        float r = sqrtf(fmaf(alpha, alpha, dx * dx));
        float pol = fast_atan2f(r, gamma);
        float phi = fast_atan2f(dx, alpha);
        float gy = pol * gy_scale - 0.5f;
        int iy0 = __float2int_rd(gy);
        float fy = gy - (float)iy0;
        int iy1 = min(iy0 + 1, HH - 1);
        iy0 = max(iy0, 0);
        float4 m;
        m.x = phi * gx_scale;
        m.y = fy;
        m.z = __int_as_float(iy0 * WW);
        m.w = __int_as_float(iy1 * WW);
        s_map[ty][k] = m;
    }
    __syncthreads();

    float wf = (float)(blockIdx.x * 32 + threadIdx.x);
    int w = blockIdx.x * 32 + threadIdx.x;
    int h = blockIdx.y * 8 + threadIdx.y;
    int ty = threadIdx.y;

    unsigned long long a0[4] = {0ull, 0ull, 0ull, 0ull};
    unsigned long long a1[4] = {0ull, 0ull, 0ull, 0ull};

    const ulonglong2* wsp = reinterpret_cast<const ulonglong2*>(ws);

#pragma unroll
    for (int k = 0; k < KK; k++) {
        float4 m = s_map[ty][k];
        float gx = wf + m.x;
        int ix0 = __float2int_rd(gx);
        float fx = gx - (float)ix0;
        int ix1 = (ix0 + 1) & (WW - 1);   // power-of-2 wrap handles any range
        ix0 &= (WW - 1);
        float fy = m.y;
        int iy0o = __float_as_int(m.z);
        int iy1o = __float_as_int(m.w);

        float wx0 = 1.0f - fx;
        float fy0 = 1.0f - fy;
        __half2 hw00 = __float2half2_rn(wx0 * fy0);
        __half2 hw01 = __float2half2_rn(fx * fy0);
        __half2 hw10 = __float2half2_rn(wx0 * fy);
        __half2 hw11 = __float2half2_rn(fx * fy);

        int i00 = iy0o + ix0;
        int i01 = iy0o + ix1;
        int i10 = iy1o + ix0;
        int i11 = iy1o + ix1;

        uint4 q00 = g_h[i00],       q01 = g_h[i01];
        uint4 q10 = g_h[i10],       q11 = g_h[i11];
        uint4 r00 = g_h[HW + i00],  r01 = g_h[HW + i01];
        uint4 r10 = g_h[HW + i10],  r11 = g_h[HW + i11];

        float v0[8], v1[8];
        bilin8(q00, q01, q10, q11, hw00, hw01, hw10, hw11, v0);
        bilin8(r00, r01, r10, r11, hw00, hw01, hw10, hw11, v1);

        const ulonglong2* wk = wsp + k * 16;
#pragma unroll
        for (int c = 0; c < CC; c++) {
            ulonglong2 wa = wk[c * 2 + 0];
            ulonglong2 wb = wk[c * 2 + 1];
            unsigned long long vd0 = dup_f32x2(v0[c]);
            unsigned long long vd1 = dup_f32x2(v1[c]);
            ffma2(a0[0], vd0, wa.x);
            ffma2(a0[1], vd0, wa.y);
            ffma2(a0[2], vd0, wb.x);
            ffma2(a0[3], vd0, wb.y);
            ffma2(a1[0], vd1, wa.x);
            ffma2(a1[1], vd1, wa.y);
            ffma2(a1[2], vd1, wb.x);
            ffma2(a1[3], vd1, wb.y);
        }
    }

#pragma unroll
    for (int j = 0; j < 4; j++) {
        float l0, h0, l1, h1;
        asm("mov.b64 {%0, %1}, %2;" : "=f"(l0), "=f"(h0) : "l"(a0[j]));
        asm("mov.b64 {%0, %1}, %2;" : "=f"(l1), "=f"(h1) : "l"(a1[j]));
        int o = 2 * j;
        out[(size_t)((0 * OC + o) * HH + h) * WW + w]     = l0 + sb[o];
        out[(size_t)((0 * OC + o + 1) * HH + h) * WW + w] = h0 + sb[o + 1];
        out[(size_t)((1 * OC + o) * HH + h) * WW + w]     = l1 + sb[o];
        out[(size_t)((1 * OC + o + 1) * HH + h) * WW + w] = h1 + sb[o + 1];
    }
}

extern "C" void kernel_launch(void* const* d_in, const int* in_sizes, int n_in,
                              void* d_out, int out_size) {
    const float* x = (const float*)d_in[0];
    const float* wgt = (const float*)d_in[1];
    const float* bias = (const float*)d_in[2];
    float* out = (float*)d_out;

    int npix = BB * HW;
    transpose_h<<<(npix + 255) / 256, 256>>>(x);

    dim3 block(32, 8);
    dim3 grid(WW / 32, HH / 8);
    sconv_kernel<<<grid, block>>>(wgt, bias, out);
}